// round 13
// baseline (speedup 1.0000x reference)
#include <cuda_runtime.h>
#include <cuda_pipeline.h>
#include <math.h>

#define B 16384
#define TDEC 12

typedef unsigned long long ull;

// P[e][b][i] = dot(comb_W[i][0:128], enc[e][b][:]) — 12.6 MB scratch (L2-resident)
__device__ __align__(16) float g_P[48 * B * 4];

__constant__ float cAW[48 * 36];   // attn_W raw row-major
__constant__ float cAb[48];
__constant__ float cWhh[96 * 32];  // raw row-major
__constant__ float cWih[96 * 4];
__constant__ float cBih[96];
__constant__ float cBhh[96];
__constant__ float cCWx[16];       // comb_W[i][128..131]
__constant__ float cCb[4];
__constant__ float cFcW[32];
__constant__ float cFcb[1];

// ---- f32x2 packed math (sm_103a) ----
__device__ __forceinline__ ull fma2(ull a, ull b, ull c) {
    ull d;
    asm("fma.rn.f32x2 %0, %1, %2, %3;" : "=l"(d) : "l"(a), "l"(b), "l"(c));
    return d;
}
__device__ __forceinline__ ull add2(ull a, ull b) {
    ull d;
    asm("add.rn.f32x2 %0, %1, %2;" : "=l"(d) : "l"(a), "l"(b));
    return d;
}
__device__ __forceinline__ ull pk2(float lo, float hi) {
    ull r;
    asm("mov.b64 %0, {%1, %2};" : "=l"(r) : "f"(lo), "f"(hi));
    return r;
}
__device__ __forceinline__ float2 upk2(ull v) {
    float2 f;
    asm("mov.b64 {%0, %1}, %2;" : "=f"(f.x), "=f"(f.y) : "l"(v));
    return f;
}
__device__ __forceinline__ float tanh_ap(float x) {
    float r;
    asm("tanh.approx.f32 %0, %1;" : "=f"(r) : "f"(x));
    return r;
}
__device__ __forceinline__ float nfix(float v) {
    if (isnan(v)) return 0.f;
    return fminf(fmaxf(v, -3.4028234663852886e38f), 3.4028234663852886e38f);
}

// ====== kernel 1: cp.async double-buffered P precompute (measured 80us) ======
__global__ __launch_bounds__(256) void precompute_P(const float* __restrict__ enc,
                                                    const float* __restrict__ comb_W)
{
    __shared__ __align__(16) float tile[2][64 * 132];
    __shared__ __align__(16) float wT[33 * 20];

    const int tid = threadIdx.x;
    const int w = tid >> 5;
    const int lane = tid & 31;

    for (int idx = tid; idx < 512; idx += 256) {
        int q = idx >> 4, i = (idx >> 2) & 3, j = idx & 3;
        wT[q * 20 + i * 4 + j] = comb_W[i * 132 + q * 4 + j];
    }

    const size_t base = (size_t)blockIdx.x * 256;
    const float4* ebase = (const float4*)enc;

#pragma unroll
    for (int r = 0; r < 8; r++) {
        size_t row = base + w * 8 + r;
        __pipeline_memcpy_async(&tile[0][(w * 8 + r) * 132 + lane * 4],
                                &ebase[row * 32 + lane], 16);
    }
    __pipeline_commit();

    for (int ti = 0; ti < 4; ti++) {
        const int buf = ti & 1;
        __pipeline_wait_prior(0);
        __syncthreads();
        if (ti < 3) {
#pragma unroll
            for (int r = 0; r < 8; r++) {
                size_t row = base + (size_t)(ti + 1) * 64 + w * 8 + r;
                __pipeline_memcpy_async(&tile[buf ^ 1][(w * 8 + r) * 132 + lane * 4],
                                        &ebase[row * 32 + lane], 16);
            }
            __pipeline_commit();
        }

        const int rl = w * 8 + (lane >> 2);
        const int c = lane & 3;
        float s0 = 0.f, s1 = 0.f, s2 = 0.f, s3 = 0.f;
#pragma unroll
        for (int k = 0; k < 8; k++) {
            int kp = (k + 2 * c) & 7;
            int q = 8 * c + kp;
            float4 v  = *(const float4*)&tile[buf][rl * 132 + q * 4];
            float4 w0 = *(const float4*)&wT[q * 20 + 0];
            float4 w1 = *(const float4*)&wT[q * 20 + 4];
            float4 w2 = *(const float4*)&wT[q * 20 + 8];
            float4 w3 = *(const float4*)&wT[q * 20 + 12];
            s0 = fmaf(v.x, w0.x, s0); s0 = fmaf(v.y, w0.y, s0); s0 = fmaf(v.z, w0.z, s0); s0 = fmaf(v.w, w0.w, s0);
            s1 = fmaf(v.x, w1.x, s1); s1 = fmaf(v.y, w1.y, s1); s1 = fmaf(v.z, w1.z, s1); s1 = fmaf(v.w, w1.w, s1);
            s2 = fmaf(v.x, w2.x, s2); s2 = fmaf(v.y, w2.y, s2); s2 = fmaf(v.z, w2.z, s2); s2 = fmaf(v.w, w2.w, s2);
            s3 = fmaf(v.x, w3.x, s3); s3 = fmaf(v.y, w3.y, s3); s3 = fmaf(v.z, w3.z, s3); s3 = fmaf(v.w, w3.w, s3);
        }
        s0 += __shfl_xor_sync(0xffffffffu, s0, 1); s0 += __shfl_xor_sync(0xffffffffu, s0, 2);
        s1 += __shfl_xor_sync(0xffffffffu, s1, 1); s1 += __shfl_xor_sync(0xffffffffu, s1, 2);
        s2 += __shfl_xor_sync(0xffffffffu, s2, 1); s2 += __shfl_xor_sync(0xffffffffu, s2, 2);
        s3 += __shfl_xor_sync(0xffffffffu, s3, 1); s3 += __shfl_xor_sync(0xffffffffu, s3, 2);

        float v = s0;
        if (c == 1) v = s1; else if (c == 2) v = s2; else if (c == 3) v = s3;
        g_P[(base + (size_t)ti * 64) * 4 + w * 32 + lane] = v;
        __syncthreads();
    }
}

// ====== kernel 2: element-per-lane, weights on constant port, 4-warp rows ====
// smem float offsets
#define P_OFF   0                      // P[e][elem] float4: 48*32
#define RB_OFF  6144                   // h buffer: 32 elems x 36 floats
#define PB_OFF  7296                   // partials: 4 warps x 32 x 8 floats
#define PO_OFF  8320                   // fc partials: 4 x 32
#define SMEM_FLOATS 8448

__global__ __launch_bounds__(128, 4)
void decoder_loop(const float* __restrict__ y,
                  const float* __restrict__ hidden,
                  float* __restrict__ out)
{
    __shared__ __align__(16) float dsm[SMEM_FLOATS];
    const int tid = threadIdx.x;
    const int w = tid >> 5;
    const int lane = tid & 31;
    const int b0blk = blockIdx.x * 32;
    const int b = b0blk + lane;

    // stage P slice: P[e][elem] (L2-resident scratch)
    {
        float4* Pd = (float4*)&dsm[P_OFF];
        const float4* gP4 = (const float4*)g_P;
        for (int i = tid; i < 48 * 32; i += 128)
            Pd[i] = __ldg(&gP4[(size_t)(i >> 5) * B + b0blk + (i & 31)]);
    }
    // stage h buffer (element column stride 36, conflict-free)
    for (int i = tid; i < 32 * 32; i += 128)
        dsm[RB_OFF + (i >> 5) * 36 + (i & 31)] = hidden[(size_t)b0blk * 32 + i];
    __syncthreads();

    // per-lane full h packed in f32x2 pairs
    ull hp[16];
#pragma unroll
    for (int q = 0; q < 8; q++) {
        float4 hv = *(const float4*)(hidden + (size_t)b * 32 + 4 * q);
        hp[2 * q + 0] = pk2(hv.x, hv.y);
        hp[2 * q + 1] = pk2(hv.z, hv.w);
    }

    float4 yv = *(const float4*)(y + (size_t)b * 52);
    float xA = nfix(yv.x), xB = nfix(yv.y), xC = nfix(yv.z), xD = nfix(yv.w);

    const ulonglong2* aw4  = (const ulonglong2*)cAW;    // 9 per row (144B rows)
    const ulonglong2* whh4 = (const ulonglong2*)cWhh;   // 8 per row
    const ulonglong2* wih4 = (const ulonglong2*)cWih;   // 1 per row
    const ulonglong2* Pw2  = (const ulonglong2*)&dsm[P_OFF];
    float* rbuf = &dsm[RB_OFF + lane * 36];
    const ulonglong2* rb2 = (const ulonglong2*)rbuf;

    for (int t = 0; t < TDEC; t++) {
        ull xab = pk2(xA, xB), xcd = pk2(xC, xD);

        // ---- attn: warp w owns rows e = 12w..12w+11 ----
        float ss = 0.f;
        ull c01 = 0, c23 = 0;
#pragma unroll
        for (int j = 0; j < 12; j++) {
            const int e = 12 * w + j;
            const ulonglong2* ar = aw4 + e * 9;
            ulonglong2 w0 = ar[0];
            ull acc2 = fma2(xab, w0.x, 0ull);
            acc2 = fma2(xcd, w0.y, acc2);
#pragma unroll
            for (int q = 0; q < 8; q++) {
                ulonglong2 wv = ar[1 + q];
                acc2 = fma2(hp[2 * q + 0], wv.x, acc2);
                acc2 = fma2(hp[2 * q + 1], wv.y, acc2);
            }
            float2 ac = upk2(acc2);
            float ev = __expf(ac.x + ac.y + cAb[e]);
            ss += ev;
            ull evv = pk2(ev, ev);
            ulonglong2 pv = Pw2[e * 32 + lane];
            c01 = fma2(evv, pv.x, c01);
            c23 = fma2(evv, pv.y, c23);
        }
        // exchange partials across 4 warps
        {
            float* pb = &dsm[PB_OFF + (w * 32 + lane) * 8];
            pb[0] = ss;
            *(ull*)(pb + 2) = c01;
            *(ull*)(pb + 4) = c23;
        }
        __syncthreads();   // B1
        float sst = 0.f;
        ull C01 = 0, C23 = 0;
#pragma unroll
        for (int ww = 0; ww < 4; ww++) {
            const float* pq = &dsm[PB_OFF + (ww * 32 + lane) * 8];
            sst += pq[0];
            C01 = add2(C01, *(const ull*)(pq + 2));
            C23 = add2(C23, *(const ull*)(pq + 4));
        }

        // ---- X (per lane) ----
        float inv = __fdividef(1.f, sst);
        float2 cA = upk2(C01), cB = upk2(C23);
        float4 cw0 = *(const float4*)&cCWx[0];
        float4 cw1 = *(const float4*)&cCWx[4];
        float4 cw2 = *(const float4*)&cCWx[8];
        float4 cw3 = *(const float4*)&cCWx[12];
        float X0 = fmaf(cA.x, inv, cCb[0]);
        X0 = fmaf(xA, cw0.x, X0); X0 = fmaf(xB, cw0.y, X0); X0 = fmaf(xC, cw0.z, X0); X0 = fmaf(xD, cw0.w, X0);
        float X1 = fmaf(cA.y, inv, cCb[1]);
        X1 = fmaf(xA, cw1.x, X1); X1 = fmaf(xB, cw1.y, X1); X1 = fmaf(xC, cw1.z, X1); X1 = fmaf(xD, cw1.w, X1);
        float X2 = fmaf(cB.x, inv, cCb[2]);
        X2 = fmaf(xA, cw2.x, X2); X2 = fmaf(xB, cw2.y, X2); X2 = fmaf(xC, cw2.z, X2); X2 = fmaf(xD, cw2.w, X2);
        float X3 = fmaf(cB.y, inv, cCb[3]);
        X3 = fmaf(xA, cw3.x, X3); X3 = fmaf(xB, cw3.y, X3); X3 = fmaf(xC, cw3.z, X3); X3 = fmaf(xD, cw3.w, X3);
        ull X01 = pk2(X0, X1), X23 = pk2(X2, X3);

        // ---- GRU: warp w owns h-rows r0 = 8w..8w+7 (3 gates each) ----
        float po = 0.f;
#pragma unroll
        for (int i = 0; i < 8; i++) {
            const int r0 = 8 * w + i;
            const int rz = 32 + r0, rn = 64 + r0;

            ulonglong2 wiR = wih4[r0];
            ull a2 = fma2(X01, wiR.x, 0ull);
            a2 = fma2(X23, wiR.y, a2);
            ulonglong2 wiZ = wih4[rz];
            ull z2 = fma2(X01, wiZ.x, 0ull);
            z2 = fma2(X23, wiZ.y, z2);
            ulonglong2 wiN = wih4[rn];
            ull i2 = fma2(X01, wiN.x, 0ull);
            i2 = fma2(X23, wiN.y, i2);
            ull n2 = 0;
#pragma unroll
            for (int q = 0; q < 8; q++) {
                ulonglong2 wr = whh4[r0 * 8 + q];
                a2 = fma2(hp[2 * q + 0], wr.x, a2);
                a2 = fma2(hp[2 * q + 1], wr.y, a2);
                ulonglong2 wz = whh4[rz * 8 + q];
                z2 = fma2(hp[2 * q + 0], wz.x, z2);
                z2 = fma2(hp[2 * q + 1], wz.y, z2);
                ulonglong2 wn = whh4[rn * 8 + q];
                n2 = fma2(hp[2 * q + 0], wn.x, n2);
                n2 = fma2(hp[2 * q + 1], wn.y, n2);
            }
            float2 au = upk2(a2), zu = upk2(z2), iu = upk2(i2), nu = upk2(n2);
            float sr = au.x + au.y + cBih[r0] + cBhh[r0];
            float sz = zu.x + zu.y + cBih[rz] + cBhh[rz];
            float gi = iu.x + iu.y + cBih[rn];
            float gh = nu.x + nu.y + cBhh[rn];

            float r = fmaf(tanh_ap(0.5f * sr), 0.5f, 0.5f);
            float z = fmaf(tanh_ap(0.5f * sz), 0.5f, 0.5f);
            float n = tanh_ap(fmaf(r, gh, gi));
            float hold = rbuf[r0];            // previous h[r0] (this warp owns it)
            float hnew = fmaf(z, hold - n, n);
            rbuf[r0] = hnew;
            po = fmaf(hnew, cFcW[r0], po);
        }
        dsm[PO_OFF + w * 32 + lane] = po;
        __syncthreads();   // B2

        // ---- rebuild hp, finish fc, advance x ----
        float o = cFcb[0] + ((dsm[PO_OFF + 0 * 32 + lane] + dsm[PO_OFF + 1 * 32 + lane]) +
                             (dsm[PO_OFF + 2 * 32 + lane] + dsm[PO_OFF + 3 * 32 + lane]));
#pragma unroll
        for (int q = 0; q < 8; q++) {
            ulonglong2 hv = rb2[q];
            hp[2 * q + 0] = hv.x;
            hp[2 * q + 1] = hv.y;
        }
        if (w == 0) out[(size_t)t * B + b] = o;
        if (t < TDEC - 1) {
            float4 yn = *(const float4*)(y + (size_t)b * 52 + (t + 1) * 4);
            xA = yn.y; xB = yn.z; xC = yn.w; xD = o;
        }
        __syncthreads();   // protect rbuf/PB before next step's writes
    }
}

extern "C" void kernel_launch(void* const* d_in, const int* in_sizes, int n_in,
                              void* d_out, int out_size) {
    const float* y      = (const float*)d_in[0];
    const float* enc    = (const float*)d_in[1];
    const float* hidden = (const float*)d_in[2];
    // d_in[3] = batch_ids (unused)
    const float* attn_W = (const float*)d_in[4];
    const float* attn_b = (const float*)d_in[5];
    const float* comb_W = (const float*)d_in[6];
    const float* comb_b = (const float*)d_in[7];
    const float* w_ih   = (const float*)d_in[8];
    const float* w_hh   = (const float*)d_in[9];
    const float* b_ih   = (const float*)d_in[10];
    const float* b_hh   = (const float*)d_in[11];
    const float* fc_W   = (const float*)d_in[12];
    const float* fc_b   = (const float*)d_in[13];

    void *pAW, *pAb, *pWhh, *pWih, *pBih, *pBhh, *pCWx, *pCb, *pFcW, *pFcb;
    cudaGetSymbolAddress(&pAW,  cAW);
    cudaGetSymbolAddress(&pAb,  cAb);
    cudaGetSymbolAddress(&pWhh, cWhh);
    cudaGetSymbolAddress(&pWih, cWih);
    cudaGetSymbolAddress(&pBih, cBih);
    cudaGetSymbolAddress(&pBhh, cBhh);
    cudaGetSymbolAddress(&pCWx, cCWx);
    cudaGetSymbolAddress(&pCb,  cCb);
    cudaGetSymbolAddress(&pFcW, cFcW);
    cudaGetSymbolAddress(&pFcb, cFcb);

    cudaMemcpyAsync(pAW,  attn_W, 48 * 36 * 4, cudaMemcpyDeviceToDevice, 0);
    cudaMemcpyAsync(pAb,  attn_b, 48 * 4,      cudaMemcpyDeviceToDevice, 0);
    cudaMemcpyAsync(pWhh, w_hh, 96 * 32 * 4,   cudaMemcpyDeviceToDevice, 0);
    cudaMemcpyAsync(pWih, w_ih, 96 * 4 * 4,    cudaMemcpyDeviceToDevice, 0);
    cudaMemcpyAsync(pBih, b_ih, 96 * 4,        cudaMemcpyDeviceToDevice, 0);
    cudaMemcpyAsync(pBhh, b_hh, 96 * 4,        cudaMemcpyDeviceToDevice, 0);
    cudaMemcpy2DAsync(pCWx, 16, (const char*)comb_W + 512, 528, 16, 4,
                      cudaMemcpyDeviceToDevice, 0);
    cudaMemcpyAsync(pCb,  comb_b, 4 * 4, cudaMemcpyDeviceToDevice, 0);
    cudaMemcpyAsync(pFcW, fc_W, 32 * 4,  cudaMemcpyDeviceToDevice, 0);
    cudaMemcpyAsync(pFcb, fc_b, 4,       cudaMemcpyDeviceToDevice, 0);

    precompute_P<<<(48 * B) / 256, 256>>>(enc, comb_W);
    decoder_loop<<<B / 32, 128>>>(y, hidden, (float*)d_out);
}

// round 15
// speedup vs baseline: 3.5277x; 3.5277x over previous
#include <cuda_runtime.h>
#include <cuda_pipeline.h>
#include <math.h>

#define B 16384
#define TDEC 12

typedef unsigned long long ull;

// P[e][b][i] = dot(comb_W[i][0:128], enc[e][b][:]) — 12.6 MB scratch (L2-resident)
__device__ __align__(16) float g_P[48 * B * 4];

// ---- f32x2 packed math (sm_103a) ----
__device__ __forceinline__ ull fma2(ull a, ull b, ull c) {
    ull d;
    asm("fma.rn.f32x2 %0, %1, %2, %3;" : "=l"(d) : "l"(a), "l"(b), "l"(c));
    return d;
}
__device__ __forceinline__ ull add2(ull a, ull b) {
    ull d;
    asm("add.rn.f32x2 %0, %1, %2;" : "=l"(d) : "l"(a), "l"(b));
    return d;
}
__device__ __forceinline__ ull pk2(float lo, float hi) {
    ull r;
    asm("mov.b64 %0, {%1, %2};" : "=l"(r) : "f"(lo), "f"(hi));
    return r;
}
__device__ __forceinline__ float2 upk2(ull v) {
    float2 f;
    asm("mov.b64 {%0, %1}, %2;" : "=f"(f.x), "=f"(f.y) : "l"(v));
    return f;
}
__device__ __forceinline__ float tanh_ap(float x) {
    float r;
    asm("tanh.approx.f32 %0, %1;" : "=f"(r) : "f"(x));
    return r;
}
__device__ __forceinline__ float nfix(float v) {
    if (isnan(v)) return 0.f;
    return fminf(fmaxf(v, -3.4028234663852886e38f), 3.4028234663852886e38f);
}

// ====== kernel 1: cp.async double-buffered P precompute (measured 80us) ======
__global__ __launch_bounds__(256) void precompute_P(const float* __restrict__ enc,
                                                    const float* __restrict__ comb_W)
{
    __shared__ __align__(16) float tile[2][64 * 132];
    __shared__ __align__(16) float wT[33 * 20];

    const int tid = threadIdx.x;
    const int w = tid >> 5;
    const int lane = tid & 31;

    for (int idx = tid; idx < 512; idx += 256) {
        int q = idx >> 4, i = (idx >> 2) & 3, j = idx & 3;
        wT[q * 20 + i * 4 + j] = comb_W[i * 132 + q * 4 + j];
    }

    const size_t base = (size_t)blockIdx.x * 256;
    const float4* ebase = (const float4*)enc;

#pragma unroll
    for (int r = 0; r < 8; r++) {
        size_t row = base + w * 8 + r;
        __pipeline_memcpy_async(&tile[0][(w * 8 + r) * 132 + lane * 4],
                                &ebase[row * 32 + lane], 16);
    }
    __pipeline_commit();

    for (int ti = 0; ti < 4; ti++) {
        const int buf = ti & 1;
        __pipeline_wait_prior(0);
        __syncthreads();
        if (ti < 3) {
#pragma unroll
            for (int r = 0; r < 8; r++) {
                size_t row = base + (size_t)(ti + 1) * 64 + w * 8 + r;
                __pipeline_memcpy_async(&tile[buf ^ 1][(w * 8 + r) * 132 + lane * 4],
                                        &ebase[row * 32 + lane], 16);
            }
            __pipeline_commit();
        }

        const int rl = w * 8 + (lane >> 2);
        const int c = lane & 3;
        float s0 = 0.f, s1 = 0.f, s2 = 0.f, s3 = 0.f;
#pragma unroll
        for (int k = 0; k < 8; k++) {
            int kp = (k + 2 * c) & 7;
            int q = 8 * c + kp;
            float4 v  = *(const float4*)&tile[buf][rl * 132 + q * 4];
            float4 w0 = *(const float4*)&wT[q * 20 + 0];
            float4 w1 = *(const float4*)&wT[q * 20 + 4];
            float4 w2 = *(const float4*)&wT[q * 20 + 8];
            float4 w3 = *(const float4*)&wT[q * 20 + 12];
            s0 = fmaf(v.x, w0.x, s0); s0 = fmaf(v.y, w0.y, s0); s0 = fmaf(v.z, w0.z, s0); s0 = fmaf(v.w, w0.w, s0);
            s1 = fmaf(v.x, w1.x, s1); s1 = fmaf(v.y, w1.y, s1); s1 = fmaf(v.z, w1.z, s1); s1 = fmaf(v.w, w1.w, s1);
            s2 = fmaf(v.x, w2.x, s2); s2 = fmaf(v.y, w2.y, s2); s2 = fmaf(v.z, w2.z, s2); s2 = fmaf(v.w, w2.w, s2);
            s3 = fmaf(v.x, w3.x, s3); s3 = fmaf(v.y, w3.y, s3); s3 = fmaf(v.z, w3.z, s3); s3 = fmaf(v.w, w3.w, s3);
        }
        s0 += __shfl_xor_sync(0xffffffffu, s0, 1); s0 += __shfl_xor_sync(0xffffffffu, s0, 2);
        s1 += __shfl_xor_sync(0xffffffffu, s1, 1); s1 += __shfl_xor_sync(0xffffffffu, s1, 2);
        s2 += __shfl_xor_sync(0xffffffffu, s2, 1); s2 += __shfl_xor_sync(0xffffffffu, s2, 2);
        s3 += __shfl_xor_sync(0xffffffffu, s3, 1); s3 += __shfl_xor_sync(0xffffffffu, s3, 2);

        float v = s0;
        if (c == 1) v = s1; else if (c == 2) v = s2; else if (c == 3) v = s3;
        g_P[(base + (size_t)ti * 64) * 4 + w * 32 + lane] = v;
        __syncthreads();
    }
}

// ====== kernel 2: element-per-lane, weights via SMEM broadcast LDS ==========
// smem float offsets (all ull/float4 regions 8B/16B aligned)
#define AW_OFF   0        // attn_W raw [48][36]
#define AB_OFF   1728
#define WHH_OFF  1776     // raw [96][32]
#define WIH_OFF  4848     // raw [96][4]
#define BIH_OFF  5232
#define BHH_OFF  5328
#define CWX_OFF  5424
#define CB_OFF   5440
#define FCW_OFF  5444
#define FCB_OFF  5476
#define P_OFF    5480     // P[e][elem] float4: 48*32
#define RB_OFF   11624    // h buffer: 32 elems x 36 floats (16B-aligned rows)
#define PS_OFF   12776    // float ss[4][32]
#define PC1_OFF  12904    // ull c01[4][32]  (float offset even -> 8B aligned)
#define PC2_OFF  13160    // ull c23[4][32]
#define PO_OFF   13416    // fc partials: 4 x 32
#define SMEM_FLOATS 13544

__global__ __launch_bounds__(128)
void decoder_loop(const float* __restrict__ y,
                  const float* __restrict__ hidden,
                  const float* __restrict__ attn_W, const float* __restrict__ attn_b,
                  const float* __restrict__ comb_W, const float* __restrict__ comb_b,
                  const float* __restrict__ w_ih, const float* __restrict__ w_hh,
                  const float* __restrict__ b_ih, const float* __restrict__ b_hh,
                  const float* __restrict__ fc_W, const float* __restrict__ fc_b,
                  float* __restrict__ out)
{
    extern __shared__ __align__(16) float dsm[];
    const int tid = threadIdx.x;
    const int w = tid >> 5;
    const int lane = tid & 31;
    const int b0blk = blockIdx.x * 32;
    const int b = b0blk + lane;

    // ---- stage weights (raw layouts) ----
    for (int i = tid; i < 1728; i += 128) dsm[AW_OFF + i] = attn_W[i];
    if (tid < 48) dsm[AB_OFF + tid] = attn_b[tid];
    for (int i = tid; i < 3072; i += 128) dsm[WHH_OFF + i] = w_hh[i];
    for (int i = tid; i < 384; i += 128) dsm[WIH_OFF + i] = w_ih[i];
    if (tid < 96) { dsm[BIH_OFF + tid] = b_ih[tid]; dsm[BHH_OFF + tid] = b_hh[tid]; }
    if (tid < 16) dsm[CWX_OFF + tid] = comb_W[(tid >> 2) * 132 + 128 + (tid & 3)];
    if (tid < 4) dsm[CB_OFF + tid] = comb_b[tid];
    if (tid < 32) dsm[FCW_OFF + tid] = fc_W[tid];
    if (tid == 0) dsm[FCB_OFF] = fc_b[0];
    // stage P slice: P[e][elem]
    {
        float4* Pd = (float4*)&dsm[P_OFF];
        const float4* gP4 = (const float4*)g_P;
        for (int i = tid; i < 48 * 32; i += 128)
            Pd[i] = __ldg(&gP4[(size_t)(i >> 5) * B + b0blk + (i & 31)]);
    }
    // stage h buffer (element rows, stride 36 floats)
    for (int i = tid; i < 32 * 32; i += 128)
        dsm[RB_OFF + (i >> 5) * 36 + (i & 31)] = hidden[(size_t)b0blk * 32 + i];
    __syncthreads();

    // per-lane full h packed in f32x2 pairs
    ull hp[16];
#pragma unroll
    for (int q = 0; q < 8; q++) {
        float4 hv = *(const float4*)(hidden + (size_t)b * 32 + 4 * q);
        hp[2 * q + 0] = pk2(hv.x, hv.y);
        hp[2 * q + 1] = pk2(hv.z, hv.w);
    }

    float4 yv = *(const float4*)(y + (size_t)b * 52);
    float xA = nfix(yv.x), xB = nfix(yv.y), xC = nfix(yv.z), xD = nfix(yv.w);

    const ulonglong2* aw4  = (const ulonglong2*)&dsm[AW_OFF];    // 9 per row (144B)
    const ulonglong2* whh4 = (const ulonglong2*)&dsm[WHH_OFF];   // 8 per row
    const ulonglong2* wih4 = (const ulonglong2*)&dsm[WIH_OFF];   // 1 per row
    const ulonglong2* Pw2  = (const ulonglong2*)&dsm[P_OFF];
    float* ps  = &dsm[PS_OFF];
    ull*   pc1 = (ull*)&dsm[PC1_OFF];
    ull*   pc2 = (ull*)&dsm[PC2_OFF];
    float* rbuf = &dsm[RB_OFF + lane * 36];
    const ulonglong2* rb2 = (const ulonglong2*)rbuf;

    for (int t = 0; t < TDEC; t++) {
        ull xab = pk2(xA, xB), xcd = pk2(xC, xD);

        // ---- attn: warp w owns rows e = 12w..12w+11 (uniform-address LDS) ----
        float ss = 0.f;
        ull c01 = 0, c23 = 0;
#pragma unroll
        for (int j = 0; j < 12; j++) {
            const int e = 12 * w + j;
            const ulonglong2* ar = aw4 + e * 9;
            ulonglong2 w0 = ar[0];
            ull acc2 = fma2(xab, w0.x, 0ull);
            acc2 = fma2(xcd, w0.y, acc2);
#pragma unroll
            for (int q = 0; q < 8; q++) {
                ulonglong2 wv = ar[1 + q];
                acc2 = fma2(hp[2 * q + 0], wv.x, acc2);
                acc2 = fma2(hp[2 * q + 1], wv.y, acc2);
            }
            float2 ac = upk2(acc2);
            float ev = __expf(ac.x + ac.y + dsm[AB_OFF + e]);
            ss += ev;
            ull evv = pk2(ev, ev);
            ulonglong2 pv = Pw2[e * 32 + lane];
            c01 = fma2(evv, pv.x, c01);
            c23 = fma2(evv, pv.y, c23);
        }
        // exchange partials across 4 warps (SoA, lane-contiguous, 8B-aligned)
        ps[w * 32 + lane]  = ss;
        pc1[w * 32 + lane] = c01;
        pc2[w * 32 + lane] = c23;
        __syncthreads();   // B1
        float sst = 0.f;
        ull C01 = 0, C23 = 0;
#pragma unroll
        for (int ww = 0; ww < 4; ww++) {
            sst += ps[ww * 32 + lane];
            C01 = add2(C01, pc1[ww * 32 + lane]);
            C23 = add2(C23, pc2[ww * 32 + lane]);
        }

        // ---- X (per lane) ----
        float inv = __fdividef(1.f, sst);
        float2 cA = upk2(C01), cB = upk2(C23);
        float4 cw0 = *(const float4*)&dsm[CWX_OFF + 0];
        float4 cw1 = *(const float4*)&dsm[CWX_OFF + 4];
        float4 cw2 = *(const float4*)&dsm[CWX_OFF + 8];
        float4 cw3 = *(const float4*)&dsm[CWX_OFF + 12];
        float X0 = fmaf(cA.x, inv, dsm[CB_OFF + 0]);
        X0 = fmaf(xA, cw0.x, X0); X0 = fmaf(xB, cw0.y, X0); X0 = fmaf(xC, cw0.z, X0); X0 = fmaf(xD, cw0.w, X0);
        float X1 = fmaf(cA.y, inv, dsm[CB_OFF + 1]);
        X1 = fmaf(xA, cw1.x, X1); X1 = fmaf(xB, cw1.y, X1); X1 = fmaf(xC, cw1.z, X1); X1 = fmaf(xD, cw1.w, X1);
        float X2 = fmaf(cB.x, inv, dsm[CB_OFF + 2]);
        X2 = fmaf(xA, cw2.x, X2); X2 = fmaf(xB, cw2.y, X2); X2 = fmaf(xC, cw2.z, X2); X2 = fmaf(xD, cw2.w, X2);
        float X3 = fmaf(cB.y, inv, dsm[CB_OFF + 3]);
        X3 = fmaf(xA, cw3.x, X3); X3 = fmaf(xB, cw3.y, X3); X3 = fmaf(xC, cw3.z, X3); X3 = fmaf(xD, cw3.w, X3);
        ull X01 = pk2(X0, X1), X23 = pk2(X2, X3);

        // ---- GRU: warp w owns h-rows r0 = 8w..8w+7 (3 gates each) ----
        float po = 0.f;
#pragma unroll
        for (int i = 0; i < 8; i++) {
            const int r0 = 8 * w + i;
            const int rz = 32 + r0, rn = 64 + r0;

            ulonglong2 wiR = wih4[r0];
            ull a2 = fma2(X01, wiR.x, 0ull);
            a2 = fma2(X23, wiR.y, a2);
            ulonglong2 wiZ = wih4[rz];
            ull z2 = fma2(X01, wiZ.x, 0ull);
            z2 = fma2(X23, wiZ.y, z2);
            ulonglong2 wiN = wih4[rn];
            ull i2 = fma2(X01, wiN.x, 0ull);
            i2 = fma2(X23, wiN.y, i2);
            ull n2 = 0;
#pragma unroll
            for (int q = 0; q < 8; q++) {
                ulonglong2 wr = whh4[r0 * 8 + q];
                a2 = fma2(hp[2 * q + 0], wr.x, a2);
                a2 = fma2(hp[2 * q + 1], wr.y, a2);
                ulonglong2 wz = whh4[rz * 8 + q];
                z2 = fma2(hp[2 * q + 0], wz.x, z2);
                z2 = fma2(hp[2 * q + 1], wz.y, z2);
                ulonglong2 wn = whh4[rn * 8 + q];
                n2 = fma2(hp[2 * q + 0], wn.x, n2);
                n2 = fma2(hp[2 * q + 1], wn.y, n2);
            }
            float2 au = upk2(a2), zu = upk2(z2), iu = upk2(i2), nu = upk2(n2);
            float sr = au.x + au.y + dsm[BIH_OFF + r0] + dsm[BHH_OFF + r0];
            float sz = zu.x + zu.y + dsm[BIH_OFF + rz] + dsm[BHH_OFF + rz];
            float gi = iu.x + iu.y + dsm[BIH_OFF + rn];
            float gh = nu.x + nu.y + dsm[BHH_OFF + rn];

            float r = fmaf(tanh_ap(0.5f * sr), 0.5f, 0.5f);
            float z = fmaf(tanh_ap(0.5f * sz), 0.5f, 0.5f);
            float n = tanh_ap(fmaf(r, gh, gi));
            float hold = rbuf[r0];
            float hnew = fmaf(z, hold - n, n);
            rbuf[r0] = hnew;
            po = fmaf(hnew, dsm[FCW_OFF + r0], po);
        }
        dsm[PO_OFF + w * 32 + lane] = po;
        __syncthreads();   // B2

        // ---- rebuild hp, finish fc, advance x ----
        float o = dsm[FCB_OFF] + ((dsm[PO_OFF + 0 * 32 + lane] + dsm[PO_OFF + 1 * 32 + lane]) +
                                  (dsm[PO_OFF + 2 * 32 + lane] + dsm[PO_OFF + 3 * 32 + lane]));
#pragma unroll
        for (int q = 0; q < 8; q++) {
            ulonglong2 hv = rb2[q];
            hp[2 * q + 0] = hv.x;
            hp[2 * q + 1] = hv.y;
        }
        if (w == 0) out[(size_t)t * B + b] = o;
        if (t < TDEC - 1) {
            float4 yn = *(const float4*)(y + (size_t)b * 52 + (t + 1) * 4);
            xA = yn.y; xB = yn.z; xC = yn.w; xD = o;
        }
    }
}

extern "C" void kernel_launch(void* const* d_in, const int* in_sizes, int n_in,
                              void* d_out, int out_size) {
    const float* y      = (const float*)d_in[0];
    const float* enc    = (const float*)d_in[1];
    const float* hidden = (const float*)d_in[2];
    // d_in[3] = batch_ids (unused)
    const float* attn_W = (const float*)d_in[4];
    const float* attn_b = (const float*)d_in[5];
    const float* comb_W = (const float*)d_in[6];
    const float* comb_b = (const float*)d_in[7];
    const float* w_ih   = (const float*)d_in[8];
    const float* w_hh   = (const float*)d_in[9];
    const float* b_ih   = (const float*)d_in[10];
    const float* b_hh   = (const float*)d_in[11];
    const float* fc_W   = (const float*)d_in[12];
    const float* fc_b   = (const float*)d_in[13];

    const int smem_bytes = SMEM_FLOATS * 4;
    cudaFuncSetAttribute(decoder_loop, cudaFuncAttributeMaxDynamicSharedMemorySize,
                         smem_bytes);

    precompute_P<<<(48 * B) / 256, 256>>>(enc, comb_W);
    decoder_loop<<<B / 32, 128, smem_bytes>>>(y, hidden, attn_W, attn_b, comb_W,
                                              comb_b, w_ih, w_hh, b_ih, b_hh,
                                              fc_W, fc_b, (float*)d_out);
}